// round 1
// baseline (speedup 1.0000x reference)
#include <cuda_runtime.h>

// PersistenceLandscapeEncoder: pairs (32768,2) f32 -> landscapes (5,4096) f32.
// out[k*4096 + j] = (k+1)-th largest of min(t_j - birth_i, death_i - t_j) over i,
// floored at 0; t_j = linspace(min(birth), max(death), 4096).

#define N_PAIRS 32768
#define RES     4096
#define NLAND   5
#define WARPS_PER_BLOCK 8
#define TILE    4096   // pairs per smem tile (32 KB)

__device__ float g_tmin;
__device__ float g_tmax;

// ---------------------------------------------------------------------------
// Kernel 1: single-block min(birth) / max(death) reduction.
// ---------------------------------------------------------------------------
__global__ void minmax_kernel(const float2* __restrict__ pairs) {
    __shared__ float smn[1024];
    __shared__ float smx[1024];
    const int tid = threadIdx.x;
    float mn = 3.0e38f, mx = -3.0e38f;
    for (int i = tid; i < N_PAIRS; i += 1024) {
        float2 p = pairs[i];
        mn = fminf(mn, p.x);
        mx = fmaxf(mx, p.y);
    }
    smn[tid] = mn; smx[tid] = mx;
    __syncthreads();
    for (int s = 512; s > 0; s >>= 1) {
        if (tid < s) {
            smn[tid] = fminf(smn[tid], smn[tid + s]);
            smx[tid] = fmaxf(smx[tid], smx[tid + s]);
        }
        __syncthreads();
    }
    if (tid == 0) { g_tmin = smn[0]; g_tmax = smx[0]; }
}

// ---------------------------------------------------------------------------
// Kernel 2: warp-per-column top-5 tent scan.
//   grid = RES/WARPS_PER_BLOCK blocks x 256 threads.
//   Pairs staged through smem in TILE-sized chunks shared by all 8 warps.
//   Each lane keeps a sorted-descending top-5 in registers (init 0 => the
//   implicit max(.,0) floor of the reference falls out for free).
// ---------------------------------------------------------------------------
__global__ void __launch_bounds__(256) landscape_kernel(
    const float2* __restrict__ pairs, float* __restrict__ out)
{
    __shared__ float2 sp[TILE];

    const int warp = threadIdx.x >> 5;
    const int lane = threadIdx.x & 31;
    const int col  = blockIdx.x * WARPS_PER_BLOCK + warp;

    const float tmin = g_tmin;
    const float tmax = g_tmax;
    const float t = tmin + (float)col * ((tmax - tmin) / (float)(RES - 1));

    float top0 = 0.0f, top1 = 0.0f, top2 = 0.0f, top3 = 0.0f, top4 = 0.0f;

    for (int base = 0; base < N_PAIRS; base += TILE) {
        // Cooperative tile load: float4 = 2 pairs per load.
        const float4* __restrict__ p4 = (const float4*)(pairs + base);
        float4* s4 = (float4*)sp;
        #pragma unroll
        for (int i = 0; i < (TILE / 2) / 256; i++)
            s4[threadIdx.x + i * 256] = p4[threadIdx.x + i * 256];
        __syncthreads();

        #pragma unroll 4
        for (int i = lane; i < TILE; i += 32) {
            float2 p = sp[i];
            float v = fminf(t - p.x, p.y - t);
            if (v > top4) {                    // rare (per-lane ~3%): sorted insert
                top4 = v;
                if (top4 > top3) { float tmp = top4; top4 = top3; top3 = tmp;
                  if (top3 > top2) { tmp = top3; top3 = top2; top2 = tmp;
                    if (top2 > top1) { tmp = top2; top2 = top1; top1 = tmp;
                      if (top1 > top0) { tmp = top1; top1 = top0; top0 = tmp; }
                    }
                  }
                }
            }
        }
        __syncthreads();
    }

    // Warp butterfly merge of sorted-descending 5-lists.
    // m[k] = max(a[k], b[k], max_{i+j=k-1} min(a[i], b[j]))  (all static indices)
    float a0 = top0, a1 = top1, a2 = top2, a3 = top3, a4 = top4;
    #pragma unroll
    for (int off = 16; off >= 1; off >>= 1) {
        float b0 = __shfl_xor_sync(0xffffffffu, a0, off);
        float b1 = __shfl_xor_sync(0xffffffffu, a1, off);
        float b2 = __shfl_xor_sync(0xffffffffu, a2, off);
        float b3 = __shfl_xor_sync(0xffffffffu, a3, off);
        float b4 = __shfl_xor_sync(0xffffffffu, a4, off);

        float m0 = fmaxf(a0, b0);
        float m1 = fmaxf(fmaxf(a1, b1), fminf(a0, b0));
        float m2 = fmaxf(fmaxf(a2, b2), fmaxf(fminf(a0, b1), fminf(a1, b0)));
        float m3 = fmaxf(fmaxf(a3, b3),
                   fmaxf(fminf(a0, b2), fmaxf(fminf(a1, b1), fminf(a2, b0))));
        float m4 = fmaxf(fmaxf(a4, b4),
                   fmaxf(fmaxf(fminf(a0, b3), fminf(a1, b2)),
                         fmaxf(fminf(a2, b1), fminf(a3, b0))));
        a0 = m0; a1 = m1; a2 = m2; a3 = m3; a4 = m4;
    }

    if (lane == 0) {
        out[0 * RES + col] = a0;
        out[1 * RES + col] = a1;
        out[2 * RES + col] = a2;
        out[3 * RES + col] = a3;
        out[4 * RES + col] = a4;
    }
}

extern "C" void kernel_launch(void* const* d_in, const int* in_sizes, int n_in,
                              void* d_out, int out_size) {
    const float2* pairs = (const float2*)d_in[0];
    float* out = (float*)d_out;

    minmax_kernel<<<1, 1024>>>(pairs);
    landscape_kernel<<<RES / WARPS_PER_BLOCK, 256>>>(pairs, out);
}